// round 13
// baseline (speedup 1.0000x reference)
#include <cuda_runtime.h>
#include <cuda_bf16.h>

// Fixed shapes per setup_inputs
#define Bn 8
#define Rn 4096
#define Gn 512
#define NG 6
#define NCX 12
#define NCELL2 (NCX * NCX)     // 144 cells of 9m
#define CAP 40
#define OUTG (Gn * 35)
#define OUTW (Gn * 35 + Rn * 2)   // 26112 floats per batch row

__constant__ int   c_group[10] = {0,1,1,2,2,3,4,4,5,5};
__constant__ float c_high[10]  = {2.0f,2.5f,2.5f,3.5f,2.5f,0.5f,1.0f,1.0f,0.5f,0.5f};
__constant__ float c_med[10]   = {4.0f,4.0f,4.0f,4.0f,4.0f,2.5f,2.5f,2.5f,2.0f,2.0f};

// Static scratch (zero-init at module load; g_cnt/g_done restored each call)
__device__ float4 g_bucket[Bn * NG * NCELL2 * CAP]; // ROI buckets: x,y,score,idx bits
__device__ int    g_cnt[Bn * NG * NCELL2];          // bucket counts (== 0 on entry)
__device__ int    g_done = 0;                       // GT-block arrival counter
__device__ float4 g_roi[Bn * Rn];                   // x, y, score, meta(grp | valid<<3)
__device__ int    g_gtstart[Bn * (NCELL2 + 1)];     // GT FP-grid prefix (valid GTs)
__device__ float2 g_gtxy[Bn * Gn];                  // GT xy, cell-sorted compact

// Largest float T with sqrt_rn(T) <= t  <=>  (d2 <= T) == (sqrt_rn(d2) <= t) bit-exactly.
__device__ __forceinline__ float adjust_thresh(float t) {
    float T = __fmul_rn(t, t);
    while (__fsqrt_rn(T) > t)
        T = __int_as_float(__float_as_int(T) - 1);
    for (;;) {
        float y = __int_as_float(__float_as_int(T) + 1);
        if (__fsqrt_rn(y) <= t) T = y; else break;
    }
    return T;
}

// 12 cells of 9m over [-54, 54]; monotone, clamped; same fn for scatter & probe.
__device__ __forceinline__ int cell12(float v) {
    int c = (int)floorf((v + 54.0f) * (1.0f / 9.0f));
    return min(max(c, 0), 11);
}

// ---- K12: GT FP-grid (blocks 0..7) + ROI pack/scatter (blocks 8..135) ----
__global__ void __launch_bounds__(256)
ptl_prep_kernel(const float* __restrict__ rois,
                const float* __restrict__ scores,
                const int*   __restrict__ labels,
                const float* __restrict__ gt) {
    int tid  = threadIdx.x;
    int lane = tid & 31;
    int wid  = tid >> 5;

    if (blockIdx.x < Bn) {
        // ---- GT FP-grid: one block per batch, 2 GTs per thread ----
        int b = blockIdx.x;
        __shared__ int scnt[NCELL2];
        __shared__ int sstart[NCELL2 + 1];
        __shared__ int scur[NCELL2];
        if (tid < NCELL2) scnt[tid] = 0;
        __syncthreads();

        float gx[2], gy[2];
        bool  gvalid[2];
        int   gcell[2];
        #pragma unroll
        for (int k = 0; k < 2; k++) {
            int gi = tid + k * 256;
            const float2* gp = (const float2*)(gt + ((size_t)b * Gn + gi) * 10);
            float2 v0 = gp[0], v1 = gp[1], v2 = gp[2], v3 = gp[3], v4 = gp[4];
            gx[k] = v0.x; gy[k] = v0.y;
            float s = v0.x; s += v0.y; s += v1.x; s += v1.y; s += v2.x;
            s += v2.y; s += v3.x; s += v3.y; s += v4.x; s += v4.y;
            gvalid[k] = (s != 0.f);
            gcell[k] = cell12(v0.y) * NCX + cell12(v0.x);
            if (gvalid[k]) atomicAdd(&scnt[gcell[k]], 1);
        }
        __syncthreads();

        // warp 0: sequential-carry shuffle scan over 144 counts (5 chunks)
        if (wid == 0) {
            int carry = 0;
            #pragma unroll
            for (int c = 0; c < 5; c++) {
                int idx = c * 32 + lane;
                int v = (idx < NCELL2) ? scnt[idx] : 0;
                int s = v;
                #pragma unroll
                for (int o = 1; o < 32; o <<= 1) {
                    int t = __shfl_up_sync(0xffffffffu, s, o);
                    if (lane >= o) s += t;
                }
                if (idx < NCELL2) sstart[idx] = s - v + carry;
                carry += __shfl_sync(0xffffffffu, s, 31);
            }
            if (lane == 0) sstart[NCELL2] = carry;
        }
        __syncthreads();
        if (tid <= NCELL2) g_gtstart[b * (NCELL2 + 1) + tid] = sstart[tid];
        if (tid < NCELL2) scur[tid] = sstart[tid];
        __syncthreads();
        #pragma unroll
        for (int k = 0; k < 2; k++) {
            if (gvalid[k]) {
                int pos = atomicAdd(&scur[gcell[k]], 1);
                g_gtxy[b * Gn + pos] = make_float2(gx[k], gy[k]);
            }
        }
    } else {
        // ---- ROI pack + cell-bucket scatter: 16 blocks per batch ----
        int bb    = blockIdx.x - Bn;
        int b     = bb >> 4;
        int chunk = bb & 15;

        __shared__ float s_stage[8 * 288];    // 9 KB warp staging

        int rowbase = chunk * 256 + wid * 32;
        const float* gsrc = rois + ((size_t)b * Rn + rowbase) * 9;
        float* st = s_stage + wid * 288;
        #pragma unroll
        for (int q = 0; q < 9; q++)
            st[q * 32 + lane] = gsrc[q * 32 + lane];   // 9 coalesced 128B loads
        __syncwarp();
        const float* row = st + lane * 9;              // stride-9: conflict-free
        float x = row[0], y = row[1];
        float s = x;
        #pragma unroll
        for (int q = 1; q < 9; q++) s += row[q];
        bool valid = (s != 0.f);

        int r = rowbase + lane;
        int lab = labels[b * Rn + r];
        lab = min(max(lab, 0), 9);
        int grp = c_group[lab];
        float sc = scores[b * Rn + r];

        float4 p;
        p.x = x; p.y = y; p.z = sc;
        p.w = __int_as_float(grp | (valid ? 8 : 0));
        g_roi[b * Rn + r] = p;

        if (valid) {
            int cell = cell12(y) * NCX + cell12(x);
            int slot = (b * NG + grp) * NCELL2 + cell;
            int pos = atomicAdd(&g_cnt[slot], 1);
            if (pos < CAP) {
                float4 e; e.x = x; e.y = y; e.z = sc; e.w = __int_as_float(r);
                g_bucket[(size_t)slot * CAP + pos] = e;
            }
        }
    }
}

#define GT_BLOCKS ((Bn * Gn) / 8)      // 8 warps/block, 1 warp = 1 GT -> 512 blocks
#define FP_BLOCKS ((Bn * Rn) / 256)    // 128 blocks, thread-per-ROI

// ---- K3: GT match (speculative bucket prefetch) + FP pass + restore ----
__global__ void __launch_bounds__(256)
ptl_main_kernel(const float* __restrict__ rois,
                const float* __restrict__ gt,
                float* __restrict__ out) {
    int lane = threadIdx.x & 31;

    if (blockIdx.x < GT_BLOCKS) {
        int warp = (blockIdx.x * blockDim.x + threadIdx.x) >> 5;  // 0..4095
        int b = warp >> 9;
        int g = warp & (Gn - 1);

        // inline GT parse: lanes 0-9 hold the row
        const float* gp = gt + ((size_t)b * Gn + g) * 10;
        float gv = (lane < 10) ? __ldg(gp + lane) : 0.f;
        float gx = __shfl_sync(0xffffffffu, gv, 0);
        float gy = __shfl_sync(0xffffffffu, gv, 1);
        int cls = (int)__shfl_sync(0xffffffffu, gv, 9);
        cls = min(max(cls, 0), 9);
        int grp = c_group[cls];
        float ht = c_high[cls];             // raw thresholds; compare on sqrt(d2)
        float mt = c_med[cls];

        // cells + ALL loads issued before the validity reduce (chain-breaking)
        int cx0 = cell12(gx - 4.0625f), cx1 = cell12(gx + 4.0625f);
        int cy0 = cell12(gy - 4.0625f), cy1 = cell12(gy + 4.0625f);
        int base0 = (b * NG + grp) * NCELL2;
        int sl0 = base0 + cy0 * NCX + cx0;
        int sl1 = base0 + cy0 * NCX + cx1;
        int sl2 = base0 + cy1 * NCX + cx0;
        int sl3 = base0 + cy1 * NCX + cx1;
        // counts and per-lane bucket entries load IN PARALLEL (addresses
        // independent of counts; lane < 32 < CAP so always in-bounds)
        int n0 = __ldg(&g_cnt[sl0]);
        int n1 = __ldg(&g_cnt[sl1]);
        int n2 = __ldg(&g_cnt[sl2]);
        int n3 = __ldg(&g_cnt[sl3]);
        float4 p0 = __ldg(&g_bucket[(size_t)sl0 * CAP + lane]);
        float4 p1 = __ldg(&g_bucket[(size_t)sl1 * CAP + lane]);
        float4 p2 = __ldg(&g_bucket[(size_t)sl2 * CAP + lane]);
        float4 p3 = __ldg(&g_bucket[(size_t)sl3 * CAP + lane]);

        // validity reduce overlaps the loads above
        float ssum = gv;
        #pragma unroll
        for (int o = 16; o; o >>= 1) ssum += __shfl_xor_sync(0xffffffffu, ssum, o);
        bool gvalid = (ssum != 0.f);

        int m0 = min(n0, CAP), m1 = min(n1, CAP), m2 = min(n2, CAP), m3 = min(n3, CAP);

        unsigned long long keyH = 0ull, keyM = 0ull;

        #define PROC(P, OK)                                                        \
            if (gvalid && (OK)) {                                                  \
                float dx = __fadd_rn((P).x, -gx);                                  \
                float dy = __fadd_rn((P).y, -gy);                                  \
                float d2 = __fadd_rn(__fmul_rn(dx, dx), __fmul_rn(dy, dy));        \
                float d  = __fsqrt_rn(d2);                                         \
                if (d <= mt) {                                                     \
                    unsigned long long key =                                       \
                        ((unsigned long long)(__float_as_uint((P).z) + 1u) << 32) |\
                        (unsigned)(~__float_as_int((P).w));                        \
                    if (d <= ht) { if (key > keyH) keyH = key; }                   \
                    else         { if (key > keyM) keyM = key; }                   \
                }                                                                  \
            }

        PROC(p0, lane < m0)
        PROC(p1, lane < m1)
        PROC(p2, lane < m2)
        PROC(p3, lane < m3)

        // rare remainder: cells holding > 32 entries (CAP = 40)
        if (gvalid && (m0 > 32 || m1 > 32 || m2 > 32 || m3 > 32)) {
            for (int i = 32 + lane; i < m0; i += 32) {
                float4 q = __ldg(&g_bucket[(size_t)sl0 * CAP + i]); PROC(q, true)
            }
            for (int i = 32 + lane; i < m1; i += 32) {
                float4 q = __ldg(&g_bucket[(size_t)sl1 * CAP + i]); PROC(q, true)
            }
            for (int i = 32 + lane; i < m2; i += 32) {
                float4 q = __ldg(&g_bucket[(size_t)sl2 * CAP + i]); PROC(q, true)
            }
            for (int i = 32 + lane; i < m3; i += 32) {
                float4 q = __ldg(&g_bucket[(size_t)sl3 * CAP + i]); PROC(q, true)
            }
        }
        #undef PROC

        // REDUX argmax: max score word, then max ~idx among score winners
        unsigned shH = (unsigned)(keyH >> 32), siH = (unsigned)keyH;
        unsigned shM = (unsigned)(keyM >> 32), siM = (unsigned)keyM;
        unsigned mhH = __reduce_max_sync(0xffffffffu, shH);
        unsigned mhM = __reduce_max_sync(0xffffffffu, shM);
        unsigned miH = __reduce_max_sync(0xffffffffu, (shH == mhH) ? siH : 0u);
        unsigned miM = __reduce_max_sync(0xffffffffu, (shM == mhM) ? siM : 0u);

        bool hv = (mhH != 0u);
        bool hm = (mhM != 0u);
        bool mv = (!hv) && hm;
        bool matched = hv || mv;
        int idxH = (int)(~miH);
        int idxM = (int)(~miM);
        float scH = __uint_as_float(mhH - 1u);
        float scM = __uint_as_float(mhM - 1u);
        float gts = __shfl_sync(0xffffffffu, gv, (lane >= 22) ? (lane - 22) : 0);

        float* o = out + (size_t)b * OUTW + g * 35;
        float val;
        if (lane < 9)
            val = hv ? __ldg(rois + ((size_t)b * Rn + idxH) * 9 + lane) : 0.f;
        else if (lane == 9)
            val = hv ? fminf(__fmul_rn(__fadd_rn(1.2f, scH), 0.5f), 1.0f) : 0.f;
        else if (lane == 10)
            val = hv ? 1.f : 0.f;
        else if (lane < 20)
            val = mv ? __ldg(rois + ((size_t)b * Rn + idxM) * 9 + (lane - 11)) : 0.f;
        else if (lane == 20)
            val = mv ? scM : 0.f;
        else if (lane == 21)
            val = mv ? 1.f : 0.f;
        else
            val = matched ? gts : 0.f;
        o[lane] = val;

        if (lane < 3) {
            bool unmatched = gvalid && !hv && !hm;
            float v = 0.f;
            if (unmatched) {
                float rng = __fsqrt_rn(__fadd_rn(__fmul_rn(gx, gx), __fmul_rn(gy, gy)));
                int bucket = (rng < 30.0f) ? 0 : ((rng > 50.0f) ? 2 : 1);
                v = (bucket == lane) ? 1.f : 0.f;
            }
            o[32 + lane] = v;
        }

        // ---- restore invariant: last GT block zeroes g_cnt + g_done ----
        __syncthreads();                 // all warps' g_cnt/g_bucket reads consumed
        __shared__ int s_last;
        if (threadIdx.x == 0) {
            int v = atomicAdd(&g_done, 1);
            s_last = (v == GT_BLOCKS - 1) ? 1 : 0;
        }
        __syncthreads();
        if (s_last) {
            if (threadIdx.x == 0) g_done = 0;
            for (int i = threadIdx.x; i < Bn * NG * NCELL2; i += 256)
                g_cnt[i] = 0;
        }
    } else {
        // ---- FP pass: thread-per-ROI, probe 12x12 GT cell grid in smem ----
        int bb = blockIdx.x - GT_BLOCKS;          // 0..127
        int b  = bb >> 4;
        int r  = ((bb & 15) << 8) + threadIdx.x;

        __shared__ int    sstart[NCELL2 + 1];
        __shared__ float2 sxy[Gn];
        if (threadIdx.x <= NCELL2)
            sstart[threadIdx.x] = g_gtstart[b * (NCELL2 + 1) + threadIdx.x];
        for (int j = threadIdx.x; j < Gn; j += 256)
            sxy[j] = g_gtxy[b * Gn + j];
        __syncthreads();

        float4 p = g_roi[b * Rn + r];
        float x = p.x, y = p.y;
        float T4 = adjust_thresh(4.0f);
        int cx0 = cell12(x - 4.0625f), cx1 = cell12(x + 4.0625f);
        int cy0 = cell12(y - 4.0625f), cy1 = cell12(y + 4.0625f);
        bool found = false;
        for (int cy = cy0; cy <= cy1 && !found; cy++) {
            int s0 = sstart[cy * NCX + cx0];
            int e0 = sstart[cy * NCX + cx1 + 1];
            for (int i = s0; i < e0; i++) {
                float2 q = sxy[i];
                float dx = __fadd_rn(x, -q.x);
                float dy = __fadd_rn(y, -q.y);
                float d2 = __fadd_rn(__fmul_rn(dx, dx), __fmul_rn(dy, dy));
                if (d2 <= T4) { found = true; break; }
            }
        }
        bool fp = ((__float_as_int(p.w) & 8) != 0) && !found;
        float2 o2;
        o2.x = fp ? p.z : 0.f;
        o2.y = fp ? 1.f : 0.f;
        *(float2*)(out + (size_t)b * OUTW + OUTG + (size_t)r * 2) = o2;
    }
}

extern "C" void kernel_launch(void* const* d_in, const int* in_sizes, int n_in,
                              void* d_out, int out_size) {
    const float* rois   = (const float*)d_in[0];
    const float* scores = (const float*)d_in[1];
    const float* gt     = (const float*)d_in[2];
    const int*   labels = (const int*)d_in[3];
    float* out = (float*)d_out;

    ptl_prep_kernel<<<Bn + Bn * 16, 256>>>(rois, scores, labels, gt);
    ptl_main_kernel<<<GT_BLOCKS + FP_BLOCKS, 256>>>(rois, gt, out);
}

// round 14
// speedup vs baseline: 1.1662x; 1.1662x over previous
#include <cuda_runtime.h>
#include <cuda_bf16.h>

// Fixed shapes per setup_inputs
#define Bn 8
#define Rn 4096
#define Gn 512
#define NG 6
#define NCX 12
#define NCELL2 (NCX * NCX)     // 144 cells of 9m
#define CAP 40
#define OUTG (Gn * 35)
#define OUTW (Gn * 35 + Rn * 2)   // 26112 floats per batch row

__constant__ int   c_group[10] = {0,1,1,2,2,3,4,4,5,5};
__constant__ float c_high[10]  = {2.0f,2.5f,2.5f,3.5f,2.5f,0.5f,1.0f,1.0f,0.5f,0.5f};
__constant__ float c_med[10]   = {4.0f,4.0f,4.0f,4.0f,4.0f,2.5f,2.5f,2.5f,2.0f,2.0f};

// Static scratch (zero-init at module load; g_cnt/g_done restored each call)
__device__ float4 g_bucket[Bn * NG * NCELL2 * CAP]; // ROI buckets: x,y,score,idx bits
__device__ int    g_cnt[Bn * NG * NCELL2];          // bucket counts (== 0 on entry)
__device__ int    g_done = 0;                       // GT-block arrival counter
__device__ float4 g_roi[Bn * Rn];                   // x, y, score, meta(grp | valid<<3)
__device__ int    g_gtstart[Bn * (NCELL2 + 1)];     // GT FP-grid prefix (valid GTs)
__device__ float2 g_gtxy[Bn * Gn];                  // GT xy, cell-sorted compact

// Largest float T with sqrt_rn(T) <= t  <=>  (d2 <= T) == (sqrt_rn(d2) <= t) bit-exactly.
__device__ __forceinline__ float adjust_thresh(float t) {
    float T = __fmul_rn(t, t);
    while (__fsqrt_rn(T) > t)
        T = __int_as_float(__float_as_int(T) - 1);
    for (;;) {
        float y = __int_as_float(__float_as_int(T) + 1);
        if (__fsqrt_rn(y) <= t) T = y; else break;
    }
    return T;
}

// 12 cells of 9m over [-54, 54]; monotone, clamped; same fn for scatter & probe.
__device__ __forceinline__ int cell12(float v) {
    int c = (int)floorf((v + 54.0f) * (1.0f / 9.0f));
    return min(max(c, 0), 11);
}

// ---- K12: GT FP-grid (blocks 0..7) + ROI pack/scatter (blocks 8..135) ----
__global__ void __launch_bounds__(256)
ptl_prep_kernel(const float* __restrict__ rois,
                const float* __restrict__ scores,
                const int*   __restrict__ labels,
                const float* __restrict__ gt) {
    int tid  = threadIdx.x;
    int lane = tid & 31;
    int wid  = tid >> 5;

    if (blockIdx.x < Bn) {
        // ---- GT FP-grid: one block per batch, 2 GTs per thread ----
        int b = blockIdx.x;
        __shared__ int scnt[NCELL2];
        __shared__ int sstart[NCELL2 + 1];
        __shared__ int scur[NCELL2];
        if (tid < NCELL2) scnt[tid] = 0;
        __syncthreads();

        float gx[2], gy[2];
        bool  gvalid[2];
        int   gcell[2];
        #pragma unroll
        for (int k = 0; k < 2; k++) {
            int gi = tid + k * 256;
            const float2* gp = (const float2*)(gt + ((size_t)b * Gn + gi) * 10);
            float2 v0 = gp[0], v1 = gp[1], v2 = gp[2], v3 = gp[3], v4 = gp[4];
            gx[k] = v0.x; gy[k] = v0.y;
            float s = v0.x; s += v0.y; s += v1.x; s += v1.y; s += v2.x;
            s += v2.y; s += v3.x; s += v3.y; s += v4.x; s += v4.y;
            gvalid[k] = (s != 0.f);
            gcell[k] = cell12(v0.y) * NCX + cell12(v0.x);
            if (gvalid[k]) atomicAdd(&scnt[gcell[k]], 1);
        }
        __syncthreads();

        // warp 0: sequential-carry shuffle scan over 144 counts (5 chunks)
        if (wid == 0) {
            int carry = 0;
            #pragma unroll
            for (int c = 0; c < 5; c++) {
                int idx = c * 32 + lane;
                int v = (idx < NCELL2) ? scnt[idx] : 0;
                int s = v;
                #pragma unroll
                for (int o = 1; o < 32; o <<= 1) {
                    int t = __shfl_up_sync(0xffffffffu, s, o);
                    if (lane >= o) s += t;
                }
                if (idx < NCELL2) sstart[idx] = s - v + carry;
                carry += __shfl_sync(0xffffffffu, s, 31);
            }
            if (lane == 0) sstart[NCELL2] = carry;
        }
        __syncthreads();
        if (tid <= NCELL2) g_gtstart[b * (NCELL2 + 1) + tid] = sstart[tid];
        if (tid < NCELL2) scur[tid] = sstart[tid];
        __syncthreads();
        #pragma unroll
        for (int k = 0; k < 2; k++) {
            if (gvalid[k]) {
                int pos = atomicAdd(&scur[gcell[k]], 1);
                g_gtxy[b * Gn + pos] = make_float2(gx[k], gy[k]);
            }
        }
    } else {
        // ---- ROI pack + cell-bucket scatter: 16 blocks per batch ----
        int bb    = blockIdx.x - Bn;
        int b     = bb >> 4;
        int chunk = bb & 15;

        __shared__ float s_stage[8 * 288];    // 9 KB warp staging

        int rowbase = chunk * 256 + wid * 32;
        const float* gsrc = rois + ((size_t)b * Rn + rowbase) * 9;
        float* st = s_stage + wid * 288;
        #pragma unroll
        for (int q = 0; q < 9; q++)
            st[q * 32 + lane] = gsrc[q * 32 + lane];   // 9 coalesced 128B loads
        __syncwarp();
        const float* row = st + lane * 9;              // stride-9: conflict-free
        float x = row[0], y = row[1];
        float s = x;
        #pragma unroll
        for (int q = 1; q < 9; q++) s += row[q];
        bool valid = (s != 0.f);

        int r = rowbase + lane;
        int lab = labels[b * Rn + r];
        lab = min(max(lab, 0), 9);
        int grp = c_group[lab];
        float sc = scores[b * Rn + r];

        float4 p;
        p.x = x; p.y = y; p.z = sc;
        p.w = __int_as_float(grp | (valid ? 8 : 0));
        g_roi[b * Rn + r] = p;

        if (valid) {
            int cell = cell12(y) * NCX + cell12(x);
            int slot = (b * NG + grp) * NCELL2 + cell;
            int pos = atomicAdd(&g_cnt[slot], 1);
            if (pos < CAP) {
                float4 e; e.x = x; e.y = y; e.z = sc; e.w = __int_as_float(r);
                g_bucket[(size_t)slot * CAP + pos] = e;
            }
        }
    }
}

#define GT_BLOCKS ((Bn * Gn) / 8)      // 8 warps/block, 1 warp = 1 GT -> 512 blocks
#define FP_BLOCKS ((Bn * Rn) / 256)    // 128 blocks, thread-per-ROI

// ---- K3: GT match (hoisted count loads, bounded bucket loop) + FP + restore ----
__global__ void __launch_bounds__(256)
ptl_main_kernel(const float* __restrict__ rois,
                const float* __restrict__ gt,
                float* __restrict__ out) {
    int lane = threadIdx.x & 31;

    if (blockIdx.x < GT_BLOCKS) {
        int warp = (blockIdx.x * blockDim.x + threadIdx.x) >> 5;  // 0..4095
        int b = warp >> 9;
        int g = warp & (Gn - 1);

        // inline GT parse: lanes 0-9 hold the row
        const float* gp = gt + ((size_t)b * Gn + g) * 10;
        float gv = (lane < 10) ? __ldg(gp + lane) : 0.f;
        float gx = __shfl_sync(0xffffffffu, gv, 0);
        float gy = __shfl_sync(0xffffffffu, gv, 1);
        int cls = (int)__shfl_sync(0xffffffffu, gv, 9);
        cls = min(max(cls, 0), 9);
        int grp = c_group[cls];
        float ht = c_high[cls];             // raw thresholds; compare on sqrt(d2)
        float mt = c_med[cls];

        // cells + COUNT loads issued before the validity reduce (chain-breaking,
        // 16B/warp — harmless on invalid GTs, g_cnt is always initialized)
        int cx0 = cell12(gx - 4.0625f), cx1 = cell12(gx + 4.0625f);
        int cy0 = cell12(gy - 4.0625f), cy1 = cell12(gy + 4.0625f);
        int base0 = (b * NG + grp) * NCELL2;
        int sl0 = base0 + cy0 * NCX + cx0;
        int sl1 = base0 + cy0 * NCX + cx1;
        int sl2 = base0 + cy1 * NCX + cx0;
        int sl3 = base0 + cy1 * NCX + cx1;
        int n0 = min(__ldg(&g_cnt[sl0]), CAP);
        int n1 = min(__ldg(&g_cnt[sl1]), CAP);
        int n2 = min(__ldg(&g_cnt[sl2]), CAP);
        int n3 = min(__ldg(&g_cnt[sl3]), CAP);

        // validity reduce overlaps the count loads' L2 round-trip
        float ssum = gv;
        #pragma unroll
        for (int o = 16; o; o >>= 1) ssum += __shfl_xor_sync(0xffffffffu, ssum, o);
        bool gvalid = (ssum != 0.f);

        unsigned long long keyH = 0ull, keyM = 0ull;

        if (gvalid) {
            int o1 = n0, o2 = n0 + n1, o3 = n0 + n1 + n2, total = o3 + n3;

            for (int i = lane; i < total; i += 32) {
                int slot, rel;
                if      (i < o1) { slot = sl0; rel = i;      }
                else if (i < o2) { slot = sl1; rel = i - o1; }
                else if (i < o3) { slot = sl2; rel = i - o2; }
                else             { slot = sl3; rel = i - o3; }
                float4 p = __ldg(&g_bucket[(size_t)slot * CAP + rel]);
                float dx = __fadd_rn(p.x, -gx);
                float dy = __fadd_rn(p.y, -gy);
                float d2 = __fadd_rn(__fmul_rn(dx, dx), __fmul_rn(dy, dy));
                float d  = __fsqrt_rn(d2);           // exactly the reference compare
                if (d <= mt) {
                    unsigned long long key =
                        ((unsigned long long)(__float_as_uint(p.z) + 1u) << 32) |
                        (unsigned)(~__float_as_int(p.w));
                    if (d <= ht) { if (key > keyH) keyH = key; }
                    else         { if (key > keyM) keyM = key; }
                }
            }
        }

        // REDUX argmax: max score word, then max ~idx among score winners
        unsigned shH = (unsigned)(keyH >> 32), siH = (unsigned)keyH;
        unsigned shM = (unsigned)(keyM >> 32), siM = (unsigned)keyM;
        unsigned mhH = __reduce_max_sync(0xffffffffu, shH);
        unsigned mhM = __reduce_max_sync(0xffffffffu, shM);
        unsigned miH = __reduce_max_sync(0xffffffffu, (shH == mhH) ? siH : 0u);
        unsigned miM = __reduce_max_sync(0xffffffffu, (shM == mhM) ? siM : 0u);

        bool hv = (mhH != 0u);
        bool hm = (mhM != 0u);
        bool mv = (!hv) && hm;
        bool matched = hv || mv;
        int idxH = (int)(~miH);
        int idxM = (int)(~miM);
        float scH = __uint_as_float(mhH - 1u);
        float scM = __uint_as_float(mhM - 1u);
        float gts = __shfl_sync(0xffffffffu, gv, (lane >= 22) ? (lane - 22) : 0);

        float* o = out + (size_t)b * OUTW + g * 35;
        float val;
        if (lane < 9)
            val = hv ? __ldg(rois + ((size_t)b * Rn + idxH) * 9 + lane) : 0.f;
        else if (lane == 9)
            val = hv ? fminf(__fmul_rn(__fadd_rn(1.2f, scH), 0.5f), 1.0f) : 0.f;
        else if (lane == 10)
            val = hv ? 1.f : 0.f;
        else if (lane < 20)
            val = mv ? __ldg(rois + ((size_t)b * Rn + idxM) * 9 + (lane - 11)) : 0.f;
        else if (lane == 20)
            val = mv ? scM : 0.f;
        else if (lane == 21)
            val = mv ? 1.f : 0.f;
        else
            val = matched ? gts : 0.f;
        o[lane] = val;

        if (lane < 3) {
            bool unmatched = gvalid && !hv && !hm;
            float v = 0.f;
            if (unmatched) {
                float rng = __fsqrt_rn(__fadd_rn(__fmul_rn(gx, gx), __fmul_rn(gy, gy)));
                int bucket = (rng < 30.0f) ? 0 : ((rng > 50.0f) ? 2 : 1);
                v = (bucket == lane) ? 1.f : 0.f;
            }
            o[32 + lane] = v;
        }

        // ---- restore invariant: last GT block zeroes g_cnt + g_done ----
        __syncthreads();                 // all warps' g_cnt/g_bucket reads consumed
        __shared__ int s_last;
        if (threadIdx.x == 0) {
            int v = atomicAdd(&g_done, 1);
            s_last = (v == GT_BLOCKS - 1) ? 1 : 0;
        }
        __syncthreads();
        if (s_last) {
            if (threadIdx.x == 0) g_done = 0;
            for (int i = threadIdx.x; i < Bn * NG * NCELL2; i += 256)
                g_cnt[i] = 0;
        }
    } else {
        // ---- FP pass: thread-per-ROI, probe 12x12 GT cell grid in smem ----
        int bb = blockIdx.x - GT_BLOCKS;          // 0..127
        int b  = bb >> 4;
        int r  = ((bb & 15) << 8) + threadIdx.x;

        __shared__ int    sstart[NCELL2 + 1];
        __shared__ float2 sxy[Gn];
        if (threadIdx.x <= NCELL2)
            sstart[threadIdx.x] = g_gtstart[b * (NCELL2 + 1) + threadIdx.x];
        for (int j = threadIdx.x; j < Gn; j += 256)
            sxy[j] = g_gtxy[b * Gn + j];
        __syncthreads();

        float4 p = g_roi[b * Rn + r];
        float x = p.x, y = p.y;
        float T4 = adjust_thresh(4.0f);
        int cx0 = cell12(x - 4.0625f), cx1 = cell12(x + 4.0625f);
        int cy0 = cell12(y - 4.0625f), cy1 = cell12(y + 4.0625f);
        bool found = false;
        for (int cy = cy0; cy <= cy1 && !found; cy++) {
            int s0 = sstart[cy * NCX + cx0];
            int e0 = sstart[cy * NCX + cx1 + 1];
            for (int i = s0; i < e0; i++) {
                float2 q = sxy[i];
                float dx = __fadd_rn(x, -q.x);
                float dy = __fadd_rn(y, -q.y);
                float d2 = __fadd_rn(__fmul_rn(dx, dx), __fmul_rn(dy, dy));
                if (d2 <= T4) { found = true; break; }
            }
        }
        bool fp = ((__float_as_int(p.w) & 8) != 0) && !found;
        float2 o2;
        o2.x = fp ? p.z : 0.f;
        o2.y = fp ? 1.f : 0.f;
        *(float2*)(out + (size_t)b * OUTW + OUTG + (size_t)r * 2) = o2;
    }
}

extern "C" void kernel_launch(void* const* d_in, const int* in_sizes, int n_in,
                              void* d_out, int out_size) {
    const float* rois   = (const float*)d_in[0];
    const float* scores = (const float*)d_in[1];
    const float* gt     = (const float*)d_in[2];
    const int*   labels = (const int*)d_in[3];
    float* out = (float*)d_out;

    ptl_prep_kernel<<<Bn + Bn * 16, 256>>>(rois, scores, labels, gt);
    ptl_main_kernel<<<GT_BLOCKS + FP_BLOCKS, 256>>>(rois, gt, out);
}